// round 6
// baseline (speedup 1.0000x reference)
#include <cuda_runtime.h>
#include <cuda_bf16.h>
#include <cstdint>
#include <cstddef>

#define B_ 32
#define T_ 2048
#define W_ 1024
#define G_ 16
#define D_ 64
#define INV_TM1 (1.0f/2047.0f)

// ---------------- scratch (static device memory; no allocations) ----------------
__device__ int    g_cov[(size_t)B_ * W_ * W_];          // int32 Gram of q, upper tiles only
__device__ signed char g_q[(size_t)B_ * W_ * T_];       // int8 quantized x, TRANSPOSED [b][w][t]
__device__ float  g_rcp[B_ * W_];                       // 127/max|x| per (b,w)
__device__ float  g_mu[B_ * W_];                        // mean of q over T (q units)
__device__ float  g_f[B_ * W_];                         // 1/sqrt((diag - T*mu^2)*INV_TM1)
__device__ float  g_partial[B_ * G_];

// ---------------- 1) per-(batch, column) max|x| over T ----------------
__global__ __launch_bounds__(256) void maxabs_kernel(const float* __restrict__ x) {
    int b = blockIdx.y;
    int w = blockIdx.x * 256 + threadIdx.x;
    const float* p = x + (size_t)b * (T_ * W_) + w;
    float m = 0.f;
#pragma unroll 8
    for (int t = 0; t < T_; ++t) m = fmaxf(m, fabsf(__ldg(p + (size_t)t * W_)));
    g_rcp[b * W_ + w] = (m > 0.f) ? (127.0f / m) : 0.f;
}

// ---------------- 2) quantize to int8 + transpose -> g_q[b][w][t] ----------------
__global__ __launch_bounds__(256) void quant_t_kernel(const float* __restrict__ x) {
    __shared__ signed char s8[64][33];
    int b = blockIdx.z;
    int t0 = blockIdx.x * 64, w0 = blockIdx.y * 32;
    int tid = threadIdx.x;
    int tx = tid & 31, ty = tid >> 5;
    float r = g_rcp[b * W_ + w0 + tx];
    const float* xp = x + ((size_t)b * T_ + t0) * W_ + w0 + tx;
#pragma unroll
    for (int i = 0; i < 8; ++i) {
        int t = i * 8 + ty;
        int q = __float2int_rn(__ldg(xp + (size_t)t * W_) * r);
        q = max(-127, min(127, q));
        s8[t][tx] = (signed char)q;
    }
    __syncthreads();
    int w = tid >> 3;
#pragma unroll
    for (int j = 0; j < 2; ++j) {
        int chunk = (tid & 7) * 2 + j;          // 0..15, 4 t's each
        uint32_t v = ((uint32_t)(uint8_t)s8[chunk * 4 + 0][w])
                   | ((uint32_t)(uint8_t)s8[chunk * 4 + 1][w] << 8)
                   | ((uint32_t)(uint8_t)s8[chunk * 4 + 2][w] << 16)
                   | ((uint32_t)(uint8_t)s8[chunk * 4 + 3][w] << 24);
        *(uint32_t*)(g_q + ((size_t)(b * W_ + w0 + w)) * T_ + t0 + chunk * 4) = v;
    }
}

// ---------------- 3) per-(b,w) sum of q over T (one warp per row) ----------------
__global__ __launch_bounds__(256) void qsum_kernel() {
    int row = blockIdx.x * 8 + (threadIdx.x >> 5);   // 0..32767
    int lane = threadIdx.x & 31;
    const uint4* p = (const uint4*)(g_q + (size_t)row * T_);
    int s = 0;
#pragma unroll
    for (int j = 0; j < 4; ++j) {
        uint4 v = __ldg(p + lane + j * 32);
        s = __dp4a((int)v.x, 0x01010101, s);
        s = __dp4a((int)v.y, 0x01010101, s);
        s = __dp4a((int)v.z, 0x01010101, s);
        s = __dp4a((int)v.w, 0x01010101, s);
    }
#pragma unroll
    for (int off = 16; off > 0; off >>= 1) s += __shfl_down_sync(0xFFFFFFFF, s, off);
    if (lane == 0) g_mu[row] = (float)s * (1.0f / T_);
}

// ---------------- 4) int8 IMMA Gram: C_b = Q Q^T, upper 128x128 tiles only ----------------
#define KS2 64   // t per pipeline stage (64 bytes per row)
#define NST 3    // stages: 3 * (8KB A + 8KB B) = 48KB static smem

__device__ __forceinline__ void cp16(uint32_t saddr, const void* gptr) {
    asm volatile("cp.async.cg.shared.global [%0], [%1], 16;\n" :: "r"(saddr), "l"(gptr));
}
#define LDSM_X4(r0, r1, r2, r3, addr) \
    asm volatile("ldmatrix.sync.aligned.m8n8.x4.shared.b16 {%0,%1,%2,%3}, [%4];" \
        : "=r"(r0), "=r"(r1), "=r"(r2), "=r"(r3) : "r"(addr))

__global__ __launch_bounds__(256, 2) void cov_imma_kernel() {
    int b = blockIdx.y;
    int rem = blockIdx.x, bi = 0, nn = 8;
    while (rem >= nn) { rem -= nn; --nn; ++bi; }
    int bj = bi + rem;
    bool diag = (bi == bj);

    __shared__ __align__(1024) unsigned char smem_raw[NST * 16384];
    uint32_t sbase = (uint32_t)__cvta_generic_to_shared(smem_raw);

    const signed char* QU = g_q + ((size_t)b * W_ + bi * 128) * T_;
    const signed char* QV = g_q + ((size_t)b * W_ + bj * 128) * T_;
    int tid = threadIdx.x;

    // load coords: idx = tid*2+i -> row = idx>>2 (0..127), cc = idx&3 (16B chunk in 64B row)
    int lrow0 = (tid * 2) >> 2;           // both i share same row (idx pairs differ in cc only when tid even)...
    // generic per-i compute below instead (cheap)

    // prologue: stages 0,1
#pragma unroll
    for (int s = 0; s < NST - 1; ++s) {
        uint32_t sU = sbase + s * 16384, sV = sU + 8192;
#pragma unroll
        for (int i = 0; i < 2; ++i) {
            int idx = tid * 2 + i;
            int row = idx >> 2, cc = idx & 3;
            uint32_t so = (uint32_t)(row * 64 + ((cc ^ ((row >> 1) & 3)) << 4));
            cp16(sU + so, QU + (size_t)row * T_ + s * KS2 + cc * 16);
            if (!diag) cp16(sV + so, QV + (size_t)row * T_ + s * KS2 + cc * 16);
        }
        asm volatile("cp.async.commit_group;\n");
    }

    int acc[4][4][4];
#pragma unroll
    for (int a = 0; a < 4; ++a)
#pragma unroll
        for (int c = 0; c < 4; ++c)
#pragma unroll
            for (int r = 0; r < 4; ++r) acc[a][c][r] = 0;

    int lane = tid & 31, wid = tid >> 5;
    int wm = wid & 1, wn = wid >> 1;      // warp tile m64 x n32

    // ldmatrix lane geometry (non-trans, 16B rows)
    int tt = lane >> 3, li = lane & 7;
    // A tiles: tt -> (rowoff=(tt&1)*8, kc=tt>>1)
    int a_rowb = wm * 64 + (tt & 1) * 8 + li;       // + mi*16
    int a_kc   = tt >> 1;                            // + kstep*2
    int a_swz  = (a_rowb >> 1) & 3;                  // invariant under +mi*16
    // B tiles: tt -> (noff=(tt>>1)*8, kc=tt&1)
    int b_rowb = wn * 32 + (tt >> 1) * 8 + li;      // + nb*16
    int b_kc   = tt & 1;                             // + kstep*2
    int b_swz  = (b_rowb >> 1) & 3;

    const int NS = T_ / KS2;  // 32
    for (int s = 0; s < NS; ++s) {
        asm volatile("cp.async.wait_group 1;\n");
        __syncthreads();

        int nk = s + NST - 1;
        if (nk < NS) {
            int st = nk % NST;
            uint32_t sU = sbase + st * 16384, sV = sU + 8192;
#pragma unroll
            for (int i = 0; i < 2; ++i) {
                int idx = tid * 2 + i;
                int row = idx >> 2, cc = idx & 3;
                uint32_t so = (uint32_t)(row * 64 + ((cc ^ ((row >> 1) & 3)) << 4));
                cp16(sU + so, QU + (size_t)row * T_ + nk * KS2 + cc * 16);
                if (!diag) cp16(sV + so, QV + (size_t)row * T_ + nk * KS2 + cc * 16);
            }
            asm volatile("cp.async.commit_group;\n");
        }

        int st = s % NST;
        uint32_t sU = sbase + st * 16384;
        uint32_t sV = diag ? sU : (sU + 8192);

#pragma unroll
        for (int kstep = 0; kstep < 2; ++kstep) {
            uint32_t aF[4][4];
#pragma unroll
            for (int mi = 0; mi < 4; ++mi) {
                int row = a_rowb + mi * 16;
                int cc = kstep * 2 + a_kc;
                uint32_t addr = sU + (uint32_t)(row * 64 + ((cc ^ a_swz) << 4));
                LDSM_X4(aF[mi][0], aF[mi][1], aF[mi][2], aF[mi][3], addr);
            }
            uint32_t bF[2][4];
#pragma unroll
            for (int nb = 0; nb < 2; ++nb) {
                int row = b_rowb + nb * 16;
                int cc = kstep * 2 + b_kc;
                uint32_t addr = sV + (uint32_t)(row * 64 + ((cc ^ b_swz) << 4));
                LDSM_X4(bF[nb][0], bF[nb][1], bF[nb][2], bF[nb][3], addr);
            }
#pragma unroll
            for (int mi = 0; mi < 4; ++mi)
#pragma unroll
                for (int ni = 0; ni < 4; ++ni)
                    asm volatile("mma.sync.aligned.m16n8k32.row.col.s32.s8.s8.s32 "
                        "{%0,%1,%2,%3},{%4,%5,%6,%7},{%8,%9},{%0,%1,%2,%3};\n"
                        : "+r"(acc[mi][ni][0]), "+r"(acc[mi][ni][1]),
                          "+r"(acc[mi][ni][2]), "+r"(acc[mi][ni][3])
                        : "r"(aF[mi][0]), "r"(aF[mi][1]), "r"(aF[mi][2]), "r"(aF[mi][3]),
                          "r"(bF[ni >> 1][(ni & 1) * 2]), "r"(bF[ni >> 1][(ni & 1) * 2 + 1]));
        }
    }

    int* Cb = g_cov + (size_t)b * W_ * W_;
    int g = lane >> 2, tg = lane & 3;
#pragma unroll
    for (int mi = 0; mi < 4; ++mi) {
        int m = bi * 128 + wm * 64 + mi * 16 + g;
#pragma unroll
        for (int ni = 0; ni < 4; ++ni) {
            int n2 = bj * 128 + wn * 32 + ni * 8 + tg * 2;
            *(int2*)(Cb + (size_t)m * W_ + n2)       = make_int2(acc[mi][ni][0], acc[mi][ni][1]);
            *(int2*)(Cb + (size_t)(m + 8) * W_ + n2) = make_int2(acc[mi][ni][2], acc[mi][ni][3]);
        }
    }
}

// ---------------- 5) f = 1/sqrt((diag - T*mu^2)*INV_TM1) ----------------
__global__ __launch_bounds__(256) void f_kernel() {
    int i = blockIdx.x * 256 + threadIdx.x;    // 32768
    int b = i >> 10, w = i & 1023;
    float mu = g_mu[i];
    float var = ((float)g_cov[(size_t)b * W_ * W_ + (size_t)w * W_ + w] - (float)T_ * mu * mu) * INV_TM1;
    g_f[i] = (var > 0.f) ? rsqrtf(var) : 0.f;
}

// ---------------- 6) EMA scan over batches, upper pairs only (symmetric) ----------------
__global__ __launch_bounds__(256) void ema_kernel(const float* __restrict__ ema_in,
                                                  float* __restrict__ ema_out) {
    int v = blockIdx.x * 256 + threadIdx.x;
    int w = blockIdx.y;
    if (v < w) return;
    const int* cp = g_cov + (size_t)w * W_ + v;
    float e = __ldg(ema_in + w * W_ + v);
#pragma unroll 4
    for (int b = 0; b < B_; ++b) {
        float mw = g_mu[b * W_ + w], mv = g_mu[b * W_ + v];
        float c = ((float)__ldg(cp + (size_t)b * (W_ * W_)) - (float)T_ * mw * mv) * INV_TM1;
        float corr = c * g_f[b * W_ + w] * g_f[b * W_ + v];
        corr = fminf(1.f, fmaxf(-1.f, corr));
        if (fabsf(corr) > 0.5f) e = 0.9f * e + 0.1f * corr;
    }
    ema_out[w * W_ + v] = e;
    ema_out[v * W_ + w] = e;
}

// ---------------- 7) per-(g,b) off-diagonal |corr| partial sums ----------------
__global__ __launch_bounds__(256) void corr_partial_kernel() {
    int g = blockIdx.x, b = blockIdx.y;
    const int* covb = g_cov + (size_t)b * (W_ * W_);
    const float* fs = g_f + b * W_;
    const float* mn = g_mu + b * W_;
    int tid = threadIdx.x;
    float s = 0.f;
    for (int i = tid; i < D_ * D_; i += 256) {
        int d = i >> 6, e2 = i & 63;
        if (d == e2) continue;
        int w = g * 64 + d, v = g * 64 + e2;
        float c = ((float)covb[(size_t)w * W_ + v] - (float)T_ * mn[w] * mn[v]) * INV_TM1;
        float corr = fminf(1.f, fmaxf(-1.f, c * fs[w] * fs[v]));
        s += fabsf(corr);
    }
    __shared__ float red[256];
    red[tid] = s;
    __syncthreads();
    for (int off = 128; off > 0; off >>= 1) {
        if (tid < off) red[tid] += red[tid + off];
        __syncthreads();
    }
    if (tid == 0) g_partial[b * G_ + g] = red[0];
}

__global__ void corr_final_kernel(float* __restrict__ out_corr) {
    int g = threadIdx.x;
    if (g < G_) {
        float s = 0.f;
        for (int b = 0; b < B_; ++b) s += g_partial[b * G_ + g];  // fixed order: deterministic
        out_corr[g] = s * (1.0f / ((float)(D_ * D_ - D_) * (float)B_));
    }
}

// ---------------- 8) expert MLP: D->16(relu)->1 per group ----------------
__global__ __launch_bounds__(256) void mlp_kernel(const float* __restrict__ x,
                                                  const float* __restrict__ W1,
                                                  const float* __restrict__ b1,
                                                  const float* __restrict__ W2,
                                                  const float* __restrict__ b2,
                                                  float* __restrict__ out) {
    __shared__ __align__(16) float W1s[4096];
    __shared__ float b1s[64], W2s[64], b2s[4];
    int tid = threadIdx.x;
    int gq = blockIdx.y;
    for (int i = tid; i < 1024; i += 256)
        ((float4*)W1s)[i] = ((const float4*)(W1 + (size_t)gq * 4096))[i];
    if (tid < 64) { b1s[tid] = b1[gq * 64 + tid]; W2s[tid] = W2[gq * 64 + tid]; }
    if (tid < 4) b2s[tid] = b2[gq * 4 + tid];
    __syncthreads();

    int gsub = tid & 3, tr = tid >> 2;
    int g = gq * 4 + gsub;
    size_t row0 = (size_t)blockIdx.x * 128 + tr * 2;
    const float4* xp0 = (const float4*)(x + row0 * W_ + g * 64);
    const float4* xp1 = (const float4*)(x + (row0 + 1) * W_ + g * 64);

    float h0[16], h1[16];
#pragma unroll
    for (int h = 0; h < 16; ++h) { h0[h] = b1s[gsub * 16 + h]; h1[h] = h0[h]; }

#pragma unroll 4
    for (int d4 = 0; d4 < 16; ++d4) {
        float4 xa = __ldg(xp0 + d4);
        float4 xb = __ldg(xp1 + d4);
#pragma unroll
        for (int h = 0; h < 16; ++h) {
            float4 wv = *(float4*)&W1s[(gsub * 16 + h) * 64 + d4 * 4];
            h0[h] = fmaf(wv.x, xa.x, h0[h]); h0[h] = fmaf(wv.y, xa.y, h0[h]);
            h0[h] = fmaf(wv.z, xa.z, h0[h]); h0[h] = fmaf(wv.w, xa.w, h0[h]);
            h1[h] = fmaf(wv.x, xb.x, h1[h]); h1[h] = fmaf(wv.y, xb.y, h1[h]);
            h1[h] = fmaf(wv.z, xb.z, h1[h]); h1[h] = fmaf(wv.w, xb.w, h1[h]);
        }
    }
    float o0 = b2s[gsub], o1 = b2s[gsub];
#pragma unroll
    for (int h = 0; h < 16; ++h) {
        o0 += W2s[gsub * 16 + h] * fmaxf(h0[h], 0.f);
        o1 += W2s[gsub * 16 + h] * fmaxf(h1[h], 0.f);
    }
    out[row0 * G_ + g]       = o0;
    out[(row0 + 1) * G_ + g] = o1;
}

// ---------------- launch ----------------
extern "C" void kernel_launch(void* const* d_in, const int* in_sizes, int n_in,
                              void* d_out, int out_size) {
    (void)in_sizes; (void)n_in; (void)out_size;
    const float* x   = (const float*)d_in[0];
    const float* ema = (const float*)d_in[1];
    const float* W1  = (const float*)d_in[2];
    const float* b1  = (const float*)d_in[3];
    const float* W2  = (const float*)d_in[4];
    const float* b2  = (const float*)d_in[5];

    float* out      = (float*)d_out;                      // (B,T,G) = 1048576
    float* out_corr = out + (size_t)B_ * T_ * G_;         // (G,)    = 16
    float* out_ema  = out_corr + G_;                      // (W,W)   = 1048576

    maxabs_kernel<<<dim3(W_ / 256, B_), 256>>>(x);        // idx 0
    quant_t_kernel<<<dim3(T_ / 64, W_ / 32, B_), 256>>>(x); // idx 1
    qsum_kernel<<<(B_ * W_) / 8, 256>>>();                // idx 2
    cov_imma_kernel<<<dim3(36, B_), 256>>>();             // idx 3 (ncu captures this one)
    f_kernel<<<(B_ * W_) / 256, 256>>>();                 // idx 4
    ema_kernel<<<dim3(W_ / 256, W_), 256>>>(ema, out_ema);
    corr_partial_kernel<<<dim3(G_, B_), 256>>>();
    corr_final_kernel<<<1, 32>>>(out_corr);
    mlp_kernel<<<dim3(B_ * T_ / 128, 4), 256>>>(x, W1, b1, W2, b2, out);
}

// round 7
// speedup vs baseline: 1.4887x; 1.4887x over previous
#include <cuda_runtime.h>
#include <cuda_fp16.h>
#include <cstdint>
#include <cstddef>

#define B_ 32
#define T_ 2048
#define W_ 1024
#define G_ 16
#define D_ 64
#define INV_TM1 (1.0f/2047.0f)

// ---------------- scratch (static device memory; no allocations) ----------------
__device__ float  g_cov[(size_t)B_ * W_ * W_];          // fp32 Gram of fp16(x), upper tiles only
__device__ __half g_xh[(size_t)B_ * T_ * W_];           // fp16(x), uncentered, [b][t][w]
__device__ float  g_mu[B_ * W_];                        // mean of fp16 values over T
__device__ float  g_f[B_ * W_];                         // 1/sqrt((diag - T*mu^2)*INV_TM1)
__device__ float  g_partial[B_ * G_];

// ---------------- 1) x -> fp16 (uncentered, elementwise) ----------------
__global__ __launch_bounds__(256) void tofp16_kernel(const float* __restrict__ x) {
    size_t i4 = ((size_t)blockIdx.x * 256 + threadIdx.x) * 4;
    float4 v = *(const float4*)(x + i4);
    __half2 lo = __floats2half2_rn(v.x, v.y);
    __half2 hi = __floats2half2_rn(v.z, v.w);
    uint2 u;
    u.x = *(uint32_t*)&lo; u.y = *(uint32_t*)&hi;
    *(uint2*)(g_xh + i4) = u;
}

// ---------------- 2) per-(batch, column) mean of fp16 values over T ----------------
__global__ __launch_bounds__(256) void mean_kernel() {
    int b = blockIdx.y;
    int w = blockIdx.x * 256 + threadIdx.x;
    const __half* p = g_xh + (size_t)b * (T_ * W_) + w;
    float s1 = 0.f;
#pragma unroll 8
    for (int t = 0; t < T_; ++t) s1 += __half2float(__ldg(p + (size_t)t * W_));
    g_mu[b * W_ + w] = s1 * (1.0f / T_);
}

// ---------------- 3) fp16 mma.sync Gram (f16 accum): C_b = X^T X, upper tiles ----------------
#define KS  32   // K rows per pipeline stage
#define NST 3    // pipeline stages (3 * 2 tiles * 8KB = 48KB static smem)

__device__ __forceinline__ void cp16(uint32_t saddr, const void* gptr) {
    asm volatile("cp.async.cg.shared.global [%0], [%1], 16;\n" :: "r"(saddr), "l"(gptr));
}

__global__ __launch_bounds__(256, 3) void cov_mma_kernel() {
    int b = blockIdx.y;
    // upper-triangular tile index -> (bi, bj), 8x8 grid, 36 tiles
    int rem = blockIdx.x, bi = 0, n = 8;
    while (rem >= n) { rem -= n; --n; ++bi; }
    int bj = bi + rem;
    bool diag = (bi == bj);

    __shared__ __align__(1024) unsigned char smem_raw[NST * 16384];
    uint32_t sbase = (uint32_t)__cvta_generic_to_shared(smem_raw);

    const __half* XU = g_xh + (size_t)b * T_ * W_ + bi * 128;
    const __half* XV = g_xh + (size_t)b * T_ * W_ + bj * 128;

    int tid = threadIdx.x;

    // prologue: load stages 0..NST-2
    for (int s = 0; s < NST - 1; ++s) {
        uint32_t sU = sbase + s * 16384, sV = sU + 8192;
#pragma unroll
        for (int i = 0; i < 2; ++i) {
            int c = tid + i * 256;
            int t = c >> 4, cb = c & 15;
            uint32_t o = (uint32_t)(t * 256 + ((cb ^ (t & 7)) << 4));
            cp16(sU + o, XU + (size_t)(s * KS + t) * W_ + cb * 8);
            if (!diag) cp16(sV + o, XV + (size_t)(s * KS + t) * W_ + cb * 8);
        }
        asm volatile("cp.async.commit_group;\n");
    }

    uint32_t acc[4][4][2];   // f16x2 accumulators
#pragma unroll
    for (int a = 0; a < 4; ++a)
#pragma unroll
        for (int c = 0; c < 4; ++c) { acc[a][c][0] = 0u; acc[a][c][1] = 0u; }

    int lane = tid & 31, wid = tid >> 5;
    int wm = wid & 1, wn = wid >> 1;                      // warp tile: m64 x n32, grid 2x4
    int arow = (lane & 7) + ((lane >> 4) << 3);           // A trans-ldmatrix lane row
    int acbo = (lane >> 3) & 1;
    int brow = (lane & 7) + (((lane >> 3) & 1) << 3);     // B trans-ldmatrix lane row
    int bcbo = lane >> 4;

    const int NKB = T_ / KS;  // 64
    for (int kb = 0; kb < NKB; ++kb) {
        asm volatile("cp.async.wait_group 1;\n");
        __syncthreads();

        int nk = kb + NST - 1;
        if (nk < NKB) {
            int s = nk % NST;
            uint32_t sU = sbase + s * 16384, sV = sU + 8192;
#pragma unroll
            for (int i = 0; i < 2; ++i) {
                int c = tid + i * 256;
                int t = c >> 4, cb = c & 15;
                uint32_t o = (uint32_t)(t * 256 + ((cb ^ (t & 7)) << 4));
                cp16(sU + o, XU + (size_t)(nk * KS + t) * W_ + cb * 8);
                if (!diag) cp16(sV + o, XV + (size_t)(nk * KS + t) * W_ + cb * 8);
            }
            asm volatile("cp.async.commit_group;\n");
        }

        int st = kb % NST;
        uint32_t sU = sbase + st * 16384;
        uint32_t sVd = diag ? sU : (sU + 8192);
#pragma unroll
        for (int ks = 0; ks < KS / 16; ++ks) {
            int t0 = ks * 16;
            uint32_t a[4][4];
#pragma unroll
            for (int mi = 0; mi < 4; ++mi) {
                int cbA = ((wm * 64 + mi * 16) >> 3) + acbo;
                int row = t0 + arow;
                uint32_t addr = sU + row * 256 + ((cbA ^ (row & 7)) << 4);
                asm volatile("ldmatrix.sync.aligned.m8n8.x4.trans.shared.b16 {%0,%1,%2,%3}, [%4];\n"
                    : "=r"(a[mi][0]), "=r"(a[mi][1]), "=r"(a[mi][2]), "=r"(a[mi][3]) : "r"(addr));
            }
            uint32_t bfr[4][2];
#pragma unroll
            for (int nb = 0; nb < 2; ++nb) {
                int cbB = ((wn * 32 + nb * 16) >> 3) + bcbo;
                int row = t0 + brow;
                uint32_t addr = sVd + row * 256 + ((cbB ^ (row & 7)) << 4);
                uint32_t r0, r1, r2, r3;
                asm volatile("ldmatrix.sync.aligned.m8n8.x4.trans.shared.b16 {%0,%1,%2,%3}, [%4];\n"
                    : "=r"(r0), "=r"(r1), "=r"(r2), "=r"(r3) : "r"(addr));
                bfr[nb * 2][0] = r0; bfr[nb * 2][1] = r1;
                bfr[nb * 2 + 1][0] = r2; bfr[nb * 2 + 1][1] = r3;
            }
#pragma unroll
            for (int mi = 0; mi < 4; ++mi)
#pragma unroll
                for (int ni = 0; ni < 4; ++ni)
                    asm volatile("mma.sync.aligned.m16n8k16.row.col.f16.f16.f16.f16 "
                        "{%0,%1},{%2,%3,%4,%5},{%6,%7},{%0,%1};\n"
                        : "+r"(acc[mi][ni][0]), "+r"(acc[mi][ni][1])
                        : "r"(a[mi][0]), "r"(a[mi][1]), "r"(a[mi][2]), "r"(a[mi][3]),
                          "r"(bfr[ni][0]), "r"(bfr[ni][1]));
        }
    }

    float* Cb = g_cov + (size_t)b * W_ * W_;
    int g = lane >> 2, tg = lane & 3;
#pragma unroll
    for (int mi = 0; mi < 4; ++mi) {
        int m = bi * 128 + wm * 64 + mi * 16 + g;
#pragma unroll
        for (int ni = 0; ni < 4; ++ni) {
            int n2 = bj * 128 + wn * 32 + ni * 8 + tg * 2;
            float2 lo = __half22float2(*(const __half2*)&acc[mi][ni][0]);
            float2 hi = __half22float2(*(const __half2*)&acc[mi][ni][1]);
            *(float2*)(Cb + (size_t)m * W_ + n2)       = lo;
            *(float2*)(Cb + (size_t)(m + 8) * W_ + n2) = hi;
        }
    }
}

// ---------------- 4) f = 1/sqrt((diag - T*mu^2)*INV_TM1) ----------------
__global__ __launch_bounds__(256) void f_kernel() {
    int i = blockIdx.x * 256 + threadIdx.x;    // 32768
    int b = i >> 10, w = i & 1023;
    float mu = g_mu[i];
    float var = (g_cov[(size_t)b * W_ * W_ + (size_t)w * W_ + w] - (float)T_ * mu * mu) * INV_TM1;
    g_f[i] = (var > 0.f) ? rsqrtf(var) : 0.f;
}

// ---------------- 5) EMA scan over batches, upper pairs only (symmetric) ----------------
__global__ __launch_bounds__(256) void ema_kernel(const float* __restrict__ ema_in,
                                                  float* __restrict__ ema_out) {
    int v = blockIdx.x * 256 + threadIdx.x;
    int w = blockIdx.y;
    if (v < w) return;                          // corr/ema symmetric; mirror on write
    const float* cp = g_cov + (size_t)w * W_ + v;
    float e = __ldg(ema_in + w * W_ + v);
#pragma unroll 4
    for (int b = 0; b < B_; ++b) {
        float mw = g_mu[b * W_ + w], mv = g_mu[b * W_ + v];
        float c  = (__ldg(cp + (size_t)b * (W_ * W_)) - (float)T_ * mw * mv) * INV_TM1;
        float corr = c * g_f[b * W_ + w] * g_f[b * W_ + v];
        corr = fminf(1.f, fmaxf(-1.f, corr));
        if (fabsf(corr) > 0.5f) e = 0.9f * e + 0.1f * corr;
    }
    ema_out[w * W_ + v] = e;
    ema_out[v * W_ + w] = e;
}

// ---------------- 6) per-(g,b) off-diagonal |corr| partial sums (diag tiles) ----------------
__global__ __launch_bounds__(256) void corr_partial_kernel() {
    int g = blockIdx.x, b = blockIdx.y;
    const float* covb = g_cov + (size_t)b * (W_ * W_);
    const float* fs   = g_f + b * W_;
    const float* mn   = g_mu + b * W_;
    int tid = threadIdx.x;
    float s = 0.f;
    for (int i = tid; i < D_ * D_; i += 256) {
        int d = i >> 6, e2 = i & 63;
        if (d == e2) continue;
        int w = g * 64 + d, v = g * 64 + e2;
        float c = (covb[(size_t)w * W_ + v] - (float)T_ * mn[w] * mn[v]) * INV_TM1;
        float corr = fminf(1.f, fmaxf(-1.f, c * fs[w] * fs[v]));
        s += fabsf(corr);
    }
    __shared__ float red[256];
    red[tid] = s;
    __syncthreads();
    for (int off = 128; off > 0; off >>= 1) {
        if (tid < off) red[tid] += red[tid + off];
        __syncthreads();
    }
    if (tid == 0) g_partial[b * G_ + g] = red[0];
}

__global__ void corr_final_kernel(float* __restrict__ out_corr) {
    int g = threadIdx.x;
    if (g < G_) {
        float s = 0.f;
        for (int b = 0; b < B_; ++b) s += g_partial[b * G_ + g];  // fixed order: deterministic
        out_corr[g] = s * (1.0f / ((float)(D_ * D_ - D_) * (float)B_));
    }
}

// ---------------- 7) expert MLP: D->16(relu)->1 per group ----------------
__global__ __launch_bounds__(256) void mlp_kernel(const float* __restrict__ x,
                                                  const float* __restrict__ W1,
                                                  const float* __restrict__ b1,
                                                  const float* __restrict__ W2,
                                                  const float* __restrict__ b2,
                                                  float* __restrict__ out) {
    __shared__ __align__(16) float W1s[4096];
    __shared__ float b1s[64], W2s[64], b2s[4];
    int tid = threadIdx.x;
    int gq = blockIdx.y;
    for (int i = tid; i < 1024; i += 256)
        ((float4*)W1s)[i] = ((const float4*)(W1 + (size_t)gq * 4096))[i];
    if (tid < 64) { b1s[tid] = b1[gq * 64 + tid]; W2s[tid] = W2[gq * 64 + tid]; }
    if (tid < 4) b2s[tid] = b2[gq * 4 + tid];
    __syncthreads();

    int gsub = tid & 3, tr = tid >> 2;
    int g = gq * 4 + gsub;
    size_t row0 = (size_t)blockIdx.x * 128 + tr * 2;
    const float4* xp0 = (const float4*)(x + row0 * W_ + g * 64);
    const float4* xp1 = (const float4*)(x + (row0 + 1) * W_ + g * 64);

    float h0[16], h1[16];
#pragma unroll
    for (int h = 0; h < 16; ++h) { h0[h] = b1s[gsub * 16 + h]; h1[h] = h0[h]; }

#pragma unroll 4
    for (int d4 = 0; d4 < 16; ++d4) {
        float4 xa = __ldg(xp0 + d4);
        float4 xb = __ldg(xp1 + d4);
#pragma unroll
        for (int h = 0; h < 16; ++h) {
            float4 wv = *(float4*)&W1s[(gsub * 16 + h) * 64 + d4 * 4];
            h0[h] = fmaf(wv.x, xa.x, h0[h]); h0[h] = fmaf(wv.y, xa.y, h0[h]);
            h0[h] = fmaf(wv.z, xa.z, h0[h]); h0[h] = fmaf(wv.w, xa.w, h0[h]);
            h1[h] = fmaf(wv.x, xb.x, h1[h]); h1[h] = fmaf(wv.y, xb.y, h1[h]);
            h1[h] = fmaf(wv.z, xb.z, h1[h]); h1[h] = fmaf(wv.w, xb.w, h1[h]);
        }
    }
    float o0 = b2s[gsub], o1 = b2s[gsub];
#pragma unroll
    for (int h = 0; h < 16; ++h) {
        o0 += W2s[gsub * 16 + h] * fmaxf(h0[h], 0.f);
        o1 += W2s[gsub * 16 + h] * fmaxf(h1[h], 0.f);
    }
    out[row0 * G_ + g]       = o0;
    out[(row0 + 1) * G_ + g] = o1;
}

// ---------------- launch ----------------
extern "C" void kernel_launch(void* const* d_in, const int* in_sizes, int n_in,
                              void* d_out, int out_size) {
    (void)in_sizes; (void)n_in; (void)out_size;
    const float* x   = (const float*)d_in[0];
    const float* ema = (const float*)d_in[1];
    const float* W1  = (const float*)d_in[2];
    const float* b1  = (const float*)d_in[3];
    const float* W2  = (const float*)d_in[4];
    const float* b2  = (const float*)d_in[5];

    float* out      = (float*)d_out;                      // (B,T,G) = 1048576
    float* out_corr = out + (size_t)B_ * T_ * G_;         // (G,)    = 16
    float* out_ema  = out_corr + G_;                      // (W,W)   = 1048576

    tofp16_kernel<<<(int)((size_t)B_ * T_ * W_ / 4 / 256), 256>>>(x);   // idx 0
    mean_kernel<<<dim3(W_ / 256, B_), 256>>>();                         // idx 1
    mlp_kernel<<<dim3(B_ * T_ / 128, 4), 256>>>(x, W1, b1, W2, b2, out);// idx 2 (independent)
    cov_mma_kernel<<<dim3(36, B_), 256>>>();                            // idx 3 (ncu capture slot)
    f_kernel<<<(B_ * W_) / 256, 256>>>();
    ema_kernel<<<dim3(W_ / 256, W_), 256>>>(ema, out_ema);
    corr_partial_kernel<<<dim3(G_, B_), 256>>>();
    corr_final_kernel<<<1, 32>>>(out_corr);
}

// round 8
// speedup vs baseline: 3.2063x; 2.1537x over previous
#include <cuda_runtime.h>
#include <cuda_fp16.h>
#include <cstdint>
#include <cstddef>

#define B_ 32
#define T_ 2048
#define W_ 1024
#define G_ 16
#define D_ 64
#define INV_TM1 (1.0f/2047.0f)

// ---------------- scratch (static device memory; no allocations) ----------------
__device__ float  g_cov[(size_t)B_ * W_ * W_];          // fp32 Gram of fp16(x), upper tiles only
__device__ __half g_xh[(size_t)B_ * T_ * W_];           // fp16(x), uncentered, [b][t][w]
__device__ float  g_psum[2048 * W_];                    // per-(32-row chunk) column partial sums
__device__ float  g_mu[B_ * W_];                        // mean of fp16 values over T
__device__ float  g_f[B_ * W_];                         // 1/sqrt((diag - T*mu^2)*INV_TM1)
__device__ float  g_partial[B_ * G_];

// ---------------- 1) FUSED: x -> fp16 store + column psums + fp32 MLP ----------------
// grid: (B*T/32, 4 quads), block 256. Each block: 32 rows x 256 channels (4 groups).
__global__ __launch_bounds__(256, 4) void fused_kernel(const float* __restrict__ x,
                                                       const float* __restrict__ W1,
                                                       const float* __restrict__ b1,
                                                       const float* __restrict__ W2,
                                                       const float* __restrict__ b2,
                                                       float* __restrict__ out) {
    __shared__ __align__(16) float tile[32 * 65 * 4];   // [32 rows][65 float4] padded (33.3KB)
    __shared__ __align__(16) float W1s[4096];           // 4 groups x 16 x 64
    __shared__ float psum[4][256];
    __shared__ float opart[256];
    __shared__ float b1s[64], W2s[64], b2s[4];

    int tid  = threadIdx.x;
    int quad = blockIdx.y;
    int bchunk = blockIdx.x;                            // 0..2047
    size_t row0 = (size_t)bchunk * 32;                  // global row (b*T + t)

    // stage weights
#pragma unroll
    for (int i = 0; i < 4; ++i)
        ((float4*)W1s)[tid + i * 256] = ((const float4*)(W1 + (size_t)quad * 4096))[tid + i * 256];
    if (tid < 64) { b1s[tid] = b1[quad * 64 + tid]; W2s[tid] = W2[quad * 64 + tid]; }
    if (tid < 4)  b2s[tid]  = b2[quad * 4 + tid];

    // ---- phase 1: stream 32x256 fp32, convert+store fp16, psum of rounded vals ----
    int c4 = tid & 63, rgrp = tid >> 6;
    const float* xp = x + row0 * W_ + quad * 256;
    __half* hp = g_xh + row0 * W_ + quad * 256;
    float4 lsum = make_float4(0.f, 0.f, 0.f, 0.f);
#pragma unroll
    for (int k = 0; k < 8; ++k) {
        int r = k * 4 + rgrp;
        float4 v = __ldg((const float4*)(xp + (size_t)r * W_) + c4);
        __half2 h01 = __floats2half2_rn(v.x, v.y);
        __half2 h23 = __floats2half2_rn(v.z, v.w);
        uint2 u; u.x = *(uint32_t*)&h01; u.y = *(uint32_t*)&h23;
        *((uint2*)(hp + (size_t)r * W_) + c4) = u;
        float2 f01 = __half22float2(h01);
        float2 f23 = __half22float2(h23);
        lsum.x += f01.x; lsum.y += f01.y; lsum.z += f23.x; lsum.w += f23.y;
        ((float4*)tile)[r * 65 + c4] = v;               // raw fp32 for exact MLP
    }
    ((float4*)psum)[rgrp * 64 + c4] = lsum;
    __syncthreads();

    if (tid < 64) {                                      // deterministic 4-way reduce
        float4 a = ((float4*)psum)[tid];
        float4 bb = ((float4*)psum)[64 + tid];
        float4 c = ((float4*)psum)[128 + tid];
        float4 d = ((float4*)psum)[192 + tid];
        float4 s = make_float4(a.x + bb.x + c.x + d.x, a.y + bb.y + c.y + d.y,
                               a.z + bb.z + c.z + d.z, a.w + bb.w + c.w + d.w);
        ((float4*)(g_psum + (size_t)bchunk * W_ + quad * 256))[tid] = s;
    }

    // ---- phase 2: fp32 MLP, thread = (group, h-half, row) ----
    int g  = tid >> 6;
    int hh = (tid >> 5) & 1;
    int row = tid & 31;
    float h[8];
#pragma unroll
    for (int j = 0; j < 8; ++j) h[j] = b1s[g * 16 + hh * 8 + j];
    const float4* xr = (const float4*)tile + row * 65 + g * 16;
#pragma unroll
    for (int j4 = 0; j4 < 16; ++j4) {
        float4 xv = xr[j4];
#pragma unroll
        for (int j = 0; j < 8; ++j) {
            float4 wv = ((const float4*)W1s)[(g * 16 + hh * 8 + j) * 16 + j4];
            h[j] = fmaf(wv.x, xv.x, h[j]); h[j] = fmaf(wv.y, xv.y, h[j]);
            h[j] = fmaf(wv.z, xv.z, h[j]); h[j] = fmaf(wv.w, xv.w, h[j]);
        }
    }
    float o = 0.f;
#pragma unroll
    for (int j = 0; j < 8; ++j) o += W2s[g * 16 + hh * 8 + j] * fmaxf(h[j], 0.f);
    opart[tid] = o;
    __syncthreads();
    if (hh == 0)
        out[(row0 + row) * G_ + quad * 4 + g] = o + opart[tid + 32] + b2s[g];
}

// ---------------- 2) mean reduce: mu = (1/T) * sum_chunks psum ----------------
__global__ __launch_bounds__(256) void mean_reduce_kernel() {
    int i = blockIdx.x * 256 + threadIdx.x;    // 32768 (b,w)
    int b = i >> 10, w = i & 1023;
    float s = 0.f;
#pragma unroll 8
    for (int c = 0; c < 64; ++c) s += g_psum[(size_t)(b * 64 + c) * W_ + w];
    g_mu[i] = s * (1.0f / T_);
}

// ---------------- 3) fp16 mma.sync Gram (f16 accum): C_b = X^T X, upper tiles ----------------
#define KS  32
#define NST 3

__device__ __forceinline__ void cp16(uint32_t saddr, const void* gptr) {
    asm volatile("cp.async.cg.shared.global [%0], [%1], 16;\n" :: "r"(saddr), "l"(gptr));
}

__global__ __launch_bounds__(256, 3) void cov_mma_kernel() {
    int b = blockIdx.y;
    int rem = blockIdx.x, bi = 0, n = 8;
    while (rem >= n) { rem -= n; --n; ++bi; }
    int bj = bi + rem;
    bool diag = (bi == bj);

    __shared__ __align__(1024) unsigned char smem_raw[NST * 16384];
    uint32_t sbase = (uint32_t)__cvta_generic_to_shared(smem_raw);

    const __half* XU = g_xh + (size_t)b * T_ * W_ + bi * 128;
    const __half* XV = g_xh + (size_t)b * T_ * W_ + bj * 128;

    int tid = threadIdx.x;

    for (int s = 0; s < NST - 1; ++s) {
        uint32_t sU = sbase + s * 16384, sV = sU + 8192;
#pragma unroll
        for (int i = 0; i < 2; ++i) {
            int c = tid + i * 256;
            int t = c >> 4, cb = c & 15;
            uint32_t o = (uint32_t)(t * 256 + ((cb ^ (t & 7)) << 4));
            cp16(sU + o, XU + (size_t)(s * KS + t) * W_ + cb * 8);
            if (!diag) cp16(sV + o, XV + (size_t)(s * KS + t) * W_ + cb * 8);
        }
        asm volatile("cp.async.commit_group;\n");
    }

    uint32_t acc[4][4][2];
#pragma unroll
    for (int a = 0; a < 4; ++a)
#pragma unroll
        for (int c = 0; c < 4; ++c) { acc[a][c][0] = 0u; acc[a][c][1] = 0u; }

    int lane = tid & 31, wid = tid >> 5;
    int wm = wid & 1, wn = wid >> 1;
    int arow = (lane & 7) + ((lane >> 4) << 3);
    int acbo = (lane >> 3) & 1;
    int brow = (lane & 7) + (((lane >> 3) & 1) << 3);
    int bcbo = lane >> 4;

    const int NKB = T_ / KS;
    for (int kb = 0; kb < NKB; ++kb) {
        asm volatile("cp.async.wait_group 1;\n");
        __syncthreads();

        int nk = kb + NST - 1;
        if (nk < NKB) {
            int s = nk % NST;
            uint32_t sU = sbase + s * 16384, sV = sU + 8192;
#pragma unroll
            for (int i = 0; i < 2; ++i) {
                int c = tid + i * 256;
                int t = c >> 4, cb = c & 15;
                uint32_t o = (uint32_t)(t * 256 + ((cb ^ (t & 7)) << 4));
                cp16(sU + o, XU + (size_t)(nk * KS + t) * W_ + cb * 8);
                if (!diag) cp16(sV + o, XV + (size_t)(nk * KS + t) * W_ + cb * 8);
            }
            asm volatile("cp.async.commit_group;\n");
        }

        int st = kb % NST;
        uint32_t sU = sbase + st * 16384;
        uint32_t sVd = diag ? sU : (sU + 8192);
#pragma unroll
        for (int ks = 0; ks < KS / 16; ++ks) {
            int t0 = ks * 16;
            uint32_t a[4][4];
#pragma unroll
            for (int mi = 0; mi < 4; ++mi) {
                int cbA = ((wm * 64 + mi * 16) >> 3) + acbo;
                int row = t0 + arow;
                uint32_t addr = sU + row * 256 + ((cbA ^ (row & 7)) << 4);
                asm volatile("ldmatrix.sync.aligned.m8n8.x4.trans.shared.b16 {%0,%1,%2,%3}, [%4];\n"
                    : "=r"(a[mi][0]), "=r"(a[mi][1]), "=r"(a[mi][2]), "=r"(a[mi][3]) : "r"(addr));
            }
            uint32_t bfr[4][2];
#pragma unroll
            for (int nb = 0; nb < 2; ++nb) {
                int cbB = ((wn * 32 + nb * 16) >> 3) + bcbo;
                int row = t0 + brow;
                uint32_t addr = sVd + row * 256 + ((cbB ^ (row & 7)) << 4);
                uint32_t r0, r1, r2, r3;
                asm volatile("ldmatrix.sync.aligned.m8n8.x4.trans.shared.b16 {%0,%1,%2,%3}, [%4];\n"
                    : "=r"(r0), "=r"(r1), "=r"(r2), "=r"(r3) : "r"(addr));
                bfr[nb * 2][0] = r0; bfr[nb * 2][1] = r1;
                bfr[nb * 2 + 1][0] = r2; bfr[nb * 2 + 1][1] = r3;
            }
#pragma unroll
            for (int mi = 0; mi < 4; ++mi)
#pragma unroll
                for (int ni = 0; ni < 4; ++ni)
                    asm volatile("mma.sync.aligned.m16n8k16.row.col.f16.f16.f16.f16 "
                        "{%0,%1},{%2,%3,%4,%5},{%6,%7},{%0,%1};\n"
                        : "+r"(acc[mi][ni][0]), "+r"(acc[mi][ni][1])
                        : "r"(a[mi][0]), "r"(a[mi][1]), "r"(a[mi][2]), "r"(a[mi][3]),
                          "r"(bfr[ni][0]), "r"(bfr[ni][1]));
        }
    }

    float* Cb = g_cov + (size_t)b * W_ * W_;
    int g = lane >> 2, tg = lane & 3;
#pragma unroll
    for (int mi = 0; mi < 4; ++mi) {
        int m = bi * 128 + wm * 64 + mi * 16 + g;
#pragma unroll
        for (int ni = 0; ni < 4; ++ni) {
            int n2 = bj * 128 + wn * 32 + ni * 8 + tg * 2;
            float2 lo = __half22float2(*(const __half2*)&acc[mi][ni][0]);
            float2 hi = __half22float2(*(const __half2*)&acc[mi][ni][1]);
            *(float2*)(Cb + (size_t)m * W_ + n2)       = lo;
            *(float2*)(Cb + (size_t)(m + 8) * W_ + n2) = hi;
        }
    }
}

// ---------------- 4) f = 1/sqrt((diag - T*mu^2)*INV_TM1) ----------------
__global__ __launch_bounds__(256) void f_kernel() {
    int i = blockIdx.x * 256 + threadIdx.x;
    int b = i >> 10, w = i & 1023;
    float mu = g_mu[i];
    float var = (g_cov[(size_t)b * W_ * W_ + (size_t)w * W_ + w] - (float)T_ * mu * mu) * INV_TM1;
    g_f[i] = (var > 0.f) ? rsqrtf(var) : 0.f;
}

// ---------------- 5) EMA scan over batches, upper pairs only (symmetric) ----------------
__global__ __launch_bounds__(256) void ema_kernel(const float* __restrict__ ema_in,
                                                  float* __restrict__ ema_out) {
    int v = blockIdx.x * 256 + threadIdx.x;
    int w = blockIdx.y;
    if (v < w) return;
    const float* cp = g_cov + (size_t)w * W_ + v;
    float e = __ldg(ema_in + w * W_ + v);
#pragma unroll 4
    for (int b = 0; b < B_; ++b) {
        float mw = g_mu[b * W_ + w], mv = g_mu[b * W_ + v];
        float c  = (__ldg(cp + (size_t)b * (W_ * W_)) - (float)T_ * mw * mv) * INV_TM1;
        float corr = c * g_f[b * W_ + w] * g_f[b * W_ + v];
        corr = fminf(1.f, fmaxf(-1.f, corr));
        if (fabsf(corr) > 0.5f) e = 0.9f * e + 0.1f * corr;
    }
    ema_out[w * W_ + v] = e;
    ema_out[v * W_ + w] = e;
}

// ---------------- 6) per-(g,b) off-diagonal |corr| partial sums (diag tiles) ----------------
__global__ __launch_bounds__(256) void corr_partial_kernel() {
    int g = blockIdx.x, b = blockIdx.y;
    const float* covb = g_cov + (size_t)b * (W_ * W_);
    const float* fs   = g_f + b * W_;
    const float* mn   = g_mu + b * W_;
    int tid = threadIdx.x;
    float s = 0.f;
    for (int i = tid; i < D_ * D_; i += 256) {
        int d = i >> 6, e2 = i & 63;
        if (d == e2) continue;
        int w = g * 64 + d, v = g * 64 + e2;
        float c = (covb[(size_t)w * W_ + v] - (float)T_ * mn[w] * mn[v]) * INV_TM1;
        float corr = fminf(1.f, fmaxf(-1.f, c * fs[w] * fs[v]));
        s += fabsf(corr);
    }
    __shared__ float red[256];
    red[tid] = s;
    __syncthreads();
    for (int off = 128; off > 0; off >>= 1) {
        if (tid < off) red[tid] += red[tid + off];
        __syncthreads();
    }
    if (tid == 0) g_partial[b * G_ + g] = red[0];
}

__global__ void corr_final_kernel(float* __restrict__ out_corr) {
    int g = threadIdx.x;
    if (g < G_) {
        float s = 0.f;
        for (int b = 0; b < B_; ++b) s += g_partial[b * G_ + g];  // fixed order: deterministic
        out_corr[g] = s * (1.0f / ((float)(D_ * D_ - D_) * (float)B_));
    }
}

// ---------------- launch ----------------
extern "C" void kernel_launch(void* const* d_in, const int* in_sizes, int n_in,
                              void* d_out, int out_size) {
    (void)in_sizes; (void)n_in; (void)out_size;
    const float* x   = (const float*)d_in[0];
    const float* ema = (const float*)d_in[1];
    const float* W1  = (const float*)d_in[2];
    const float* b1  = (const float*)d_in[3];
    const float* W2  = (const float*)d_in[4];
    const float* b2  = (const float*)d_in[5];

    float* out      = (float*)d_out;                      // (B,T,G) = 1048576
    float* out_corr = out + (size_t)B_ * T_ * G_;         // (G,)    = 16
    float* out_ema  = out_corr + G_;                      // (W,W)   = 1048576

    fused_kernel<<<dim3(B_ * T_ / 32, 4), 256>>>(x, W1, b1, W2, b2, out);   // idx 0
    mean_reduce_kernel<<<(B_ * W_) / 256, 256>>>();                         // idx 1
    cov_mma_kernel<<<dim3(36, B_), 256>>>();                                // idx 2
    f_kernel<<<(B_ * W_) / 256, 256>>>();                                   // idx 3
    ema_kernel<<<dim3(W_ / 256, W_), 256>>>(ema, out_ema);
    corr_partial_kernel<<<dim3(G_, B_), 256>>>();
    corr_final_kernel<<<1, 32>>>(out_corr);
}